// round 12
// baseline (speedup 1.0000x reference)
#include <cuda_runtime.h>
#include <cuda_bf16.h>
#include <math.h>
#include <stdint.h>

// Problem constants
#define NB 4
#define NQ 1024
#define NK 1024
#define ND 256
#define NH 8
#define NC 32
#define NM (NB*NQ)
#define HC (NH*NC)

#define QW 16              // words per row of packed q/k (32 channels / 2)

// Scratch (device globals)
__device__ uint32_t g_qph[NB*NH*NQ*QW];
__device__ uint32_t g_qpl[NB*NH*NQ*QW];
__device__ uint32_t g_kph[NB*NH*NK*QW];
__device__ uint32_t g_kpl[NB*NH*NK*QW];
__device__ float    g_v[NB*NH*NK*NC];
__device__ float    g_g[NM*HC];
__device__ float    g_o[NM*HC];
__device__ uint32_t g_wph[5*256*128];    // packed weights [mat][n][kw]
__device__ uint32_t g_wpl[5*256*128];

// ---------------------------------------------------------------------------
// helpers
// ---------------------------------------------------------------------------
__device__ __forceinline__ void bsplit2(float x0, float x1, uint32_t& h, uint32_t& l) {
    __nv_bfloat162 H = __floats2bfloat162_rn(x0, x1);
    float h0 = __low2float(H), h1 = __high2float(H);
    __nv_bfloat162 L = __floats2bfloat162_rn(x0 - h0, x1 - h1);
    h = *reinterpret_cast<uint32_t*>(&H);
    l = *reinterpret_cast<uint32_t*>(&L);
}
__device__ __forceinline__ void mma_bf16(float* d,
                                         uint32_t a0, uint32_t a1, uint32_t a2, uint32_t a3,
                                         uint32_t b0, uint32_t b1) {
    asm volatile(
        "mma.sync.aligned.m16n8k16.row.col.f32.bf16.bf16.f32 "
        "{%0,%1,%2,%3}, {%4,%5,%6,%7}, {%8,%9}, {%0,%1,%2,%3};\n"
        : "+f"(d[0]), "+f"(d[1]), "+f"(d[2]), "+f"(d[3])
        : "r"(a0), "r"(a1), "r"(a2), "r"(a3), "r"(b0), "r"(b1));
}

extern __shared__ float smp[];

// ---------------------------------------------------------------------------
// Kernel 0: pack weights. grid=(128,5), 256.
// ---------------------------------------------------------------------------
__global__ __launch_bounds__(256) void pack_w_kernel(
    const float* __restrict__ wq, const float* __restrict__ wk,
    const float* __restrict__ wv, const float* __restrict__ wg,
    const float* __restrict__ wo)
{
    const int mat = blockIdx.y;
    const float* W = (mat == 0) ? wq : (mat == 1) ? wk : (mat == 2) ? wv :
                     (mat == 3) ? wg : wo;
    const int id = blockIdx.x * 256 + threadIdx.x;
    const int kw = id >> 8;
    const int n  = id & 255;
    float x0 = W[(2 * kw) * 256 + n];
    float x1 = W[(2 * kw + 1) * 256 + n];
    uint32_t h, l;
    bsplit2(x0, x1, h, l);
    g_wph[mat * 32768 + n * 128 + kw] = h;
    g_wpl[mat * 32768 + n * 128 + kw] = l;
}

// ---------------------------------------------------------------------------
// Kernel 1: projections. grid=(4, 32, 4), block=256. Tile 128M x 64N, k=32.
// Warp tile 32x32. mode: 0=q,1=k,2=v,3=gate
// ---------------------------------------------------------------------------
#define GST 20

__global__ __launch_bounds__(256, 2) void proj_kernel(
    const float* __restrict__ q_x, const float* __restrict__ kv_x,
    const float* __restrict__ bg)
{
    const int mode = blockIdx.z;
    const float* A = (mode == 1 || mode == 2) ? kv_x : q_x;
    const uint32_t* WPH = g_wph + mode * 32768;
    const uint32_t* WPL = g_wpl + mode * 32768;

    uint32_t* ah_s = (uint32_t*)smp;          // [128][GST]
    uint32_t* al_s = ah_s + 128 * GST;
    uint32_t* bh_s = al_s + 128 * GST;        // [64][GST]
    uint32_t* bl_s = bh_s + 64 * GST;

    const int tid  = threadIdx.x;
    const int lane = tid & 31;
    const int wid  = tid >> 5;
    const int gid  = lane >> 2;
    const int m4   = lane & 3;
    const int wm   = wid & 3;
    const int wn   = wid >> 2;
    const int m0   = blockIdx.y * 128;
    const int n0   = blockIdx.x * 64;

    float acc[2][4][4];
#pragma unroll
    for (int mt = 0; mt < 2; mt++)
#pragma unroll
        for (int nt = 0; nt < 4; nt++)
#pragma unroll
            for (int r = 0; r < 4; r++) acc[mt][nt][r] = 0.f;

    for (int k0 = 0; k0 < ND; k0 += 32) {
        __syncthreads();
#pragma unroll
        for (int u = 0; u < 4; u++) {
            const int e  = tid + 256 * u;
            const int r  = e >> 3;
            const int kw = (e & 7) * 2;
            float4 va = *(const float4*)(A + (size_t)(m0 + r) * ND + k0 + kw * 2);
            uint32_t h0, l0, h1, l1;
            bsplit2(va.x, va.y, h0, l0);
            bsplit2(va.z, va.w, h1, l1);
            *(uint2*)(ah_s + r * GST + kw) = make_uint2(h0, h1);
            *(uint2*)(al_s + r * GST + kw) = make_uint2(l0, l1);
        }
        {
            const int nl  = tid >> 2;
            const int kw4 = (tid & 3) * 4;
            *(uint4*)(bh_s + nl * GST + kw4) =
                *(const uint4*)(WPH + (size_t)(n0 + nl) * 128 + (k0 >> 1) + kw4);
            *(uint4*)(bl_s + nl * GST + kw4) =
                *(const uint4*)(WPL + (size_t)(n0 + nl) * 128 + (k0 >> 1) + kw4);
        }
        __syncthreads();

#pragma unroll
        for (int kc = 0; kc < 2; kc++) {
            uint32_t ah[2][4], al[2][4];
#pragma unroll
            for (int mt = 0; mt < 2; mt++) {
                const int rb = wm * 32 + mt * 16 + gid;
                ah[mt][0] = ah_s[(rb)     * GST + kc * 8 + m4];
                ah[mt][1] = ah_s[(rb + 8) * GST + kc * 8 + m4];
                ah[mt][2] = ah_s[(rb)     * GST + kc * 8 + m4 + 4];
                ah[mt][3] = ah_s[(rb + 8) * GST + kc * 8 + m4 + 4];
                al[mt][0] = al_s[(rb)     * GST + kc * 8 + m4];
                al[mt][1] = al_s[(rb + 8) * GST + kc * 8 + m4];
                al[mt][2] = al_s[(rb)     * GST + kc * 8 + m4 + 4];
                al[mt][3] = al_s[(rb + 8) * GST + kc * 8 + m4 + 4];
            }
#pragma unroll
            for (int nt = 0; nt < 4; nt++) {
                const int cb = wn * 32 + nt * 8 + gid;
                uint32_t bh0 = bh_s[cb * GST + kc * 8 + m4];
                uint32_t bh1 = bh_s[cb * GST + kc * 8 + m4 + 4];
                uint32_t bl0 = bl_s[cb * GST + kc * 8 + m4];
                uint32_t bl1 = bl_s[cb * GST + kc * 8 + m4 + 4];
#pragma unroll
                for (int mt = 0; mt < 2; mt++) {
                    mma_bf16(acc[mt][nt], ah[mt][0], ah[mt][1], ah[mt][2], ah[mt][3], bh0, bh1);
                    mma_bf16(acc[mt][nt], ah[mt][0], ah[mt][1], ah[mt][2], ah[mt][3], bl0, bl1);
                    mma_bf16(acc[mt][nt], al[mt][0], al[mt][1], al[mt][2], al[mt][3], bh0, bh1);
                }
            }
        }
    }

    const float qscale = 0.17677669529663687f;
#pragma unroll
    for (int mt = 0; mt < 2; mt++) {
#pragma unroll
        for (int rr = 0; rr < 2; rr++) {
            const int row = m0 + wm * 32 + mt * 16 + gid + rr * 8;
            const int b   = row >> 10;
            const int l   = row & 1023;
#pragma unroll
            for (int nt = 0; nt < 4; nt++) {
                const int n  = n0 + wn * 32 + nt * 8 + 2 * m4;
                const int h  = n >> 5;
                const int c  = n & 31;
                float v0 = acc[mt][nt][rr * 2 + 0];
                float v1 = acc[mt][nt][rr * 2 + 1];
                if (mode == 0) {
                    uint32_t hw, lw;
                    bsplit2(v0 * qscale, v1 * qscale, hw, lw);
                    const size_t wi = (((size_t)b * NH + h) * NQ + l) * QW + (c >> 1);
                    g_qph[wi] = hw; g_qpl[wi] = lw;
                } else if (mode == 1) {
                    uint32_t hw, lw;
                    bsplit2(v0, v1, hw, lw);
                    const size_t wi = (((size_t)b * NH + h) * NK + l) * QW + (c >> 1);
                    g_kph[wi] = hw; g_kpl[wi] = lw;
                } else if (mode == 2) {
                    *(float2*)(g_v + ((((size_t)b * NH + h) * NK) + l) * NC + c) = make_float2(v0, v1);
                } else {
                    float s0 = 1.f / (1.f + __expf(-(v0 + bg[n])));
                    float s1 = 1.f / (1.f + __expf(-(v1 + bg[n + 1])));
                    *(float2*)(g_g + (size_t)row * HC + n) = make_float2(s0, s1);
                }
            }
        }
    }
}

// ---------------------------------------------------------------------------
// Kernel 2: flash attention, hi/lo-interleaved smem, register-resident P,
// register-pipelined bias_pair. grid=(8, 32), block=256, 2 CTAs/SM.
// ---------------------------------------------------------------------------
#define K2ST 20   // K tile stride in uint2
#define V2ST 37   // V tile stride in uint2

__global__ __launch_bounds__(256, 2) void attn_kernel(
    const float* __restrict__ bias_mask,   // [B, K]
    const float* __restrict__ bias_pair)   // [B, H, Q, K]
{
    uint2* kv2 = (uint2*)smp;              // [64][K2ST] (hi,lo) pairs
    uint2* v2  = kv2 + 64 * K2ST;          // [32][V2ST]
    float* bms = (float*)(v2 + 32 * V2ST); // [64]

    const int tid  = threadIdx.x;
    const int lane = tid & 31;
    const int wid  = tid >> 5;
    const int gid  = lane >> 2;
    const int m4   = lane & 3;
    const int bh   = blockIdx.y;
    const int b    = bh >> 3;
    const int h    = bh & 7;
    const int q0   = blockIdx.x * 128;
    const int r0   = q0 + wid * 16 + gid;

    // Q fragments (packed hi/lo words from gmem)
    uint32_t qh[2][4], ql[2][4];
    {
        const uint32_t* qbh = g_qph + (size_t)bh * NQ * QW;
        const uint32_t* qbl = g_qpl + (size_t)bh * NQ * QW;
#pragma unroll
        for (int kc = 0; kc < 2; kc++) {
            qh[kc][0] = qbh[(size_t)(r0)     * QW + kc * 8 + m4];
            qh[kc][1] = qbh[(size_t)(r0 + 8) * QW + kc * 8 + m4];
            qh[kc][2] = qbh[(size_t)(r0)     * QW + kc * 8 + m4 + 4];
            qh[kc][3] = qbh[(size_t)(r0 + 8) * QW + kc * 8 + m4 + 4];
            ql[kc][0] = qbl[(size_t)(r0)     * QW + kc * 8 + m4];
            ql[kc][1] = qbl[(size_t)(r0 + 8) * QW + kc * 8 + m4];
            ql[kc][2] = qbl[(size_t)(r0)     * QW + kc * 8 + m4 + 4];
            ql[kc][3] = qbl[(size_t)(r0 + 8) * QW + kc * 8 + m4 + 4];
        }
    }

    float m_i[2] = {-1e30f, -1e30f};
    float l_i[2] = {0.f, 0.f};
    float o[4][4];
#pragma unroll
    for (int nt = 0; nt < 4; nt++)
#pragma unroll
        for (int r = 0; r < 4; r++) o[nt][r] = 0.f;

    const uint32_t* kgh = g_kph + (size_t)bh * NK * QW;
    const uint32_t* kgl = g_kpl + (size_t)bh * NK * QW;
    const float*    vgb = g_v + (size_t)bh * NK * NC;
    const float*    bpb = bias_pair + ((size_t)bh * NQ + r0) * NK;
    const float*    bmb = bias_mask + (size_t)b * NK;

    // register-pipelined bias_pair: tile kt's values loaded one iter ahead
    float2 br0[8], br1[8];
#pragma unroll
    for (int nt = 0; nt < 8; nt++) {
        const int c = nt * 8 + 2 * m4;
        br0[nt] = *(const float2*)(bpb + c);
        br1[nt] = *(const float2*)(bpb + (size_t)8 * NK + c);
    }

    for (int kt = 0; kt < 16; kt++) {
        __syncthreads();   // previous iteration's readers done
        // K tile: load hi/lo uint4 pairs, store interleaved (hi,lo) uint2s
        {
            const int r   = tid >> 2;
            const int kw4 = (tid & 3) * 4;
            const size_t src = ((size_t)(kt * 64 + r)) * QW + kw4;
            uint4 H = *(const uint4*)(kgh + src);
            uint4 L = *(const uint4*)(kgl + src);
            *(uint4*)(kv2 + r * K2ST + kw4)     = make_uint4(H.x, L.x, H.y, L.y);
            *(uint4*)(kv2 + r * K2ST + kw4 + 2) = make_uint4(H.z, L.z, H.w, L.w);
        }
        // V tile: fp32 -> kv-pair packed, interleaved (hi,lo)
        {
            const float* vg = vgb + (size_t)kt * 64 * NC;
#pragma unroll
            for (int u = 0; u < 4; u++) {
                const int w  = tid + 256 * u;
                const int c  = w & 31;
                const int r2 = w >> 5;
                float x0 = vg[(2 * r2)     * NC + c];
                float x1 = vg[(2 * r2 + 1) * NC + c];
                uint32_t hw, lw;
                bsplit2(x0, x1, hw, lw);
                v2[c * V2ST + r2] = make_uint2(hw, lw);
            }
            if (tid < 64) bms[tid] = bmb[kt * 64 + tid];
        }
        __syncthreads();

        // S accumulators from pipelined bias registers + bias_mask
        float s[8][4];
#pragma unroll
        for (int nt = 0; nt < 8; nt++) {
            const int c = nt * 8 + 2 * m4;
            const float bm0 = bms[c], bm1 = bms[c + 1];
            s[nt][0] = br0[nt].x + bm0; s[nt][1] = br0[nt].y + bm1;
            s[nt][2] = br1[nt].x + bm0; s[nt][3] = br1[nt].y + bm1;
        }
        // issue next tile's bias loads now — they complete during QK/softmax/PV
        if (kt + 1 < 16) {
            const float* bp = bpb + (kt + 1) * 64;
#pragma unroll
            for (int nt = 0; nt < 8; nt++) {
                const int c = nt * 8 + 2 * m4;
                br0[nt] = *(const float2*)(bp + c);
                br1[nt] = *(const float2*)(bp + (size_t)8 * NK + c);
            }
        }

        // S += Q @ K^T   (B-fragments via LDS.64: hi+lo in one fetch)
#pragma unroll
        for (int kc = 0; kc < 2; kc++) {
#pragma unroll
            for (int nt = 0; nt < 8; nt++) {
                const int cn = nt * 8 + gid;
                uint2 p0 = kv2[cn * K2ST + kc * 8 + m4];
                uint2 p1 = kv2[cn * K2ST + kc * 8 + m4 + 4];
                mma_bf16(s[nt], qh[kc][0], qh[kc][1], qh[kc][2], qh[kc][3], p0.x, p1.x);
                mma_bf16(s[nt], qh[kc][0], qh[kc][1], qh[kc][2], qh[kc][3], p0.y, p1.y);
                mma_bf16(s[nt], ql[kc][0], ql[kc][1], ql[kc][2], ql[kc][3], p0.x, p1.x);
            }
        }

        // online softmax (rows r0, r0+8); quad-local reduction
        float mx0 = -1e30f, mx1 = -1e30f;
#pragma unroll
        for (int nt = 0; nt < 8; nt++) {
            mx0 = fmaxf(mx0, fmaxf(s[nt][0], s[nt][1]));
            mx1 = fmaxf(mx1, fmaxf(s[nt][2], s[nt][3]));
        }
#pragma unroll
        for (int off = 1; off < 4; off <<= 1) {
            mx0 = fmaxf(mx0, __shfl_xor_sync(0xffffffffu, mx0, off));
            mx1 = fmaxf(mx1, __shfl_xor_sync(0xffffffffu, mx1, off));
        }
        const float mn0 = fmaxf(m_i[0], mx0);
        const float mn1 = fmaxf(m_i[1], mx1);
        const float al0 = __expf(m_i[0] - mn0);
        const float al1 = __expf(m_i[1] - mn1);
        float sum0 = 0.f, sum1 = 0.f;
#pragma unroll
        for (int nt = 0; nt < 8; nt++) {
            s[nt][0] = __expf(s[nt][0] - mn0);
            s[nt][1] = __expf(s[nt][1] - mn0);
            s[nt][2] = __expf(s[nt][2] - mn1);
            s[nt][3] = __expf(s[nt][3] - mn1);
            sum0 += s[nt][0] + s[nt][1];
            sum1 += s[nt][2] + s[nt][3];
        }
#pragma unroll
        for (int off = 1; off < 4; off <<= 1) {
            sum0 += __shfl_xor_sync(0xffffffffu, sum0, off);
            sum1 += __shfl_xor_sync(0xffffffffu, sum1, off);
        }
        l_i[0] = l_i[0] * al0 + sum0;
        l_i[1] = l_i[1] * al1 + sum1;
        m_i[0] = mn0; m_i[1] = mn1;
#pragma unroll
        for (int nt = 0; nt < 4; nt++) {
            o[nt][0] *= al0; o[nt][1] *= al0;
            o[nt][2] *= al1; o[nt][3] *= al1;
        }

        // O += P @ V — register-resident P (S C-fragment layout == PV A-fragment)
#pragma unroll
        for (int kc = 0; kc < 4; kc++) {
            uint32_t a0h, a0l, a1h, a1l, a2h, a2l, a3h, a3l;
            bsplit2(s[2*kc][0],   s[2*kc][1],   a0h, a0l);
            bsplit2(s[2*kc][2],   s[2*kc][3],   a1h, a1l);
            bsplit2(s[2*kc+1][0], s[2*kc+1][1], a2h, a2l);
            bsplit2(s[2*kc+1][2], s[2*kc+1][3], a3h, a3l);
#pragma unroll
            for (int nt = 0; nt < 4; nt++) {
                const int cn = nt * 8 + gid;
                uint2 p0 = v2[cn * V2ST + kc * 8 + m4];
                uint2 p1 = v2[cn * V2ST + kc * 8 + m4 + 4];
                mma_bf16(o[nt], a0h, a1h, a2h, a3h, p0.x, p1.x);
                mma_bf16(o[nt], a0h, a1h, a2h, a3h, p0.y, p1.y);
                mma_bf16(o[nt], a0l, a1l, a2l, a3l, p0.x, p1.x);
            }
        }
    }

    // epilogue: normalize, write [B, Q, H, C]
    const float inv0 = 1.f / l_i[0];
    const float inv1 = 1.f / l_i[1];
#pragma unroll
    for (int nt = 0; nt < 4; nt++) {
        const int c = nt * 8 + 2 * m4;
        *(float2*)(g_o + (((size_t)b * NQ + r0)     * NH + h) * NC + c) =
            make_float2(o[nt][0] * inv0, o[nt][1] * inv0);
        *(float2*)(g_o + (((size_t)b * NQ + r0 + 8) * NH + h) * NC + c) =
            make_float2(o[nt][2] * inv1, o[nt][3] * inv1);
    }
}

// ---------------------------------------------------------------------------
// Kernel 3: out = (o * g) @ wo + bo. grid=(4, 64), block=256. Tile 64x64.
// ---------------------------------------------------------------------------
__global__ __launch_bounds__(256, 2) void out_kernel(
    const float* __restrict__ bo, float* __restrict__ out)
{
    const uint32_t* WPH = g_wph + 4 * 32768;
    const uint32_t* WPL = g_wpl + 4 * 32768;

    uint32_t* ah_s = (uint32_t*)smp;          // [64][GST]
    uint32_t* al_s = ah_s + 64 * GST;
    uint32_t* bh_s = al_s + 64 * GST;         // [64][GST]
    uint32_t* bl_s = bh_s + 64 * GST;

    const int tid  = threadIdx.x;
    const int lane = tid & 31;
    const int wid  = tid >> 5;
    const int gid  = lane >> 2;
    const int m4   = lane & 3;
    const int wm   = wid & 1;
    const int wn   = wid >> 1;
    const int m0   = blockIdx.y * 64;
    const int n0   = blockIdx.x * 64;

    float acc[2][2][4];
#pragma unroll
    for (int mt = 0; mt < 2; mt++)
#pragma unroll
        for (int nt = 0; nt < 2; nt++)
#pragma unroll
            for (int r = 0; r < 4; r++) acc[mt][nt][r] = 0.f;

    for (int k0 = 0; k0 < HC; k0 += 32) {
        __syncthreads();
#pragma unroll
        for (int u = 0; u < 2; u++) {
            const int e  = tid + 256 * u;
            const int r  = e >> 3;
            const int kw = (e & 7) * 2;
            const size_t idx = (size_t)(m0 + r) * HC + k0 + kw * 2;
            float4 va = *(const float4*)(g_o + idx);
            float4 vg = *(const float4*)(g_g + idx);
            va.x *= vg.x; va.y *= vg.y; va.z *= vg.z; va.w *= vg.w;
            uint32_t h0, l0, h1, l1;
            bsplit2(va.x, va.y, h0, l0);
            bsplit2(va.z, va.w, h1, l1);
            *(uint2*)(ah_s + r * GST + kw) = make_uint2(h0, h1);
            *(uint2*)(al_s + r * GST + kw) = make_uint2(l0, l1);
        }
        {
            const int nl  = tid >> 2;
            const int kw4 = (tid & 3) * 4;
            *(uint4*)(bh_s + nl * GST + kw4) =
                *(const uint4*)(WPH + (size_t)(n0 + nl) * 128 + (k0 >> 1) + kw4);
            *(uint4*)(bl_s + nl * GST + kw4) =
                *(const uint4*)(WPL + (size_t)(n0 + nl) * 128 + (k0 >> 1) + kw4);
        }
        __syncthreads();

#pragma unroll
        for (int kc = 0; kc < 2; kc++) {
            uint32_t ah[2][4], al[2][4];
#pragma unroll
            for (int mt = 0; mt < 2; mt++) {
                const int rb = wm * 32 + mt * 16 + gid;
                ah[mt][0] = ah_s[(rb)     * GST + kc * 8 + m4];
                ah[mt][1] = ah_s[(rb + 8) * GST + kc * 8 + m4];
                ah[mt][2] = ah_s[(rb)     * GST + kc * 8 + m4 + 4];
                ah[mt][3] = ah_s[(rb + 8) * GST + kc * 8 + m4 + 4];
                al[mt][0] = al_s[(rb)     * GST + kc * 8 + m4];
                al[mt][1] = al_s[(rb + 8) * GST + kc * 8 + m4];
                al[mt][2] = al_s[(rb)     * GST + kc * 8 + m4 + 4];
                al[mt][3] = al_s[(rb + 8) * GST + kc * 8 + m4 + 4];
            }
#pragma unroll
            for (int nt = 0; nt < 2; nt++) {
                const int cb = wn * 16 + nt * 8 + gid;
                uint32_t bh0 = bh_s[cb * GST + kc * 8 + m4];
                uint32_t bh1 = bh_s[cb * GST + kc * 8 + m4 + 4];
                uint32_t bl0 = bl_s[cb * GST + kc * 8 + m4];
                uint32_t bl1 = bl_s[cb * GST + kc * 8 + m4 + 4];
#pragma unroll
                for (int mt = 0; mt < 2; mt++) {
                    mma_bf16(acc[mt][nt], ah[mt][0], ah[mt][1], ah[mt][2], ah[mt][3], bh0, bh1);
                    mma_bf16(acc[mt][nt], ah[mt][0], ah[mt][1], ah[mt][2], ah[mt][3], bl0, bl1);
                    mma_bf16(acc[mt][nt], al[mt][0], al[mt][1], al[mt][2], al[mt][3], bh0, bh1);
                }
            }
        }
    }

#pragma unroll
    for (int mt = 0; mt < 2; mt++) {
#pragma unroll
        for (int rr = 0; rr < 2; rr++) {
            const int row = m0 + wm * 32 + mt * 16 + gid + rr * 8;
#pragma unroll
            for (int nt = 0; nt < 2; nt++) {
                const int n = n0 + wn * 16 + nt * 8 + 2 * m4;
                float v0 = acc[mt][nt][rr * 2 + 0] + bo[n];
                float v1 = acc[mt][nt][rr * 2 + 1] + bo[n + 1];
                *(float2*)(out + (size_t)row * ND + n) = make_float2(v0, v1);
            }
        }
    }
}

// ---------------------------------------------------------------------------
// Launch
// ---------------------------------------------------------------------------
extern "C" void kernel_launch(void* const* d_in, const int* in_sizes, int n_in,
                              void* d_out, int out_size)
{
    const float* q_x       = (const float*)d_in[0];
    const float* kv_x      = (const float*)d_in[1];
    const float* bias_mask = (const float*)d_in[2];
    const float* bias_pair = (const float*)d_in[3];
    const float* wq        = (const float*)d_in[4];
    const float* wk        = (const float*)d_in[5];
    const float* wv        = (const float*)d_in[6];
    const float* wg        = (const float*)d_in[7];
    const float* bg        = (const float*)d_in[8];
    const float* wo        = (const float*)d_in[9];
    const float* bo        = (const float*)d_in[10];
    float* out             = (float*)d_out;

    const int smem_proj = (2 * 128 + 2 * 64) * GST * (int)sizeof(uint32_t);   // 30720
    const int smem_attn = (64 * K2ST + 32 * V2ST) * (int)sizeof(uint2) + 64 * (int)sizeof(float); // 19968
    const int smem_out  = 4 * 64 * GST * (int)sizeof(uint32_t);               // 20480

    pack_w_kernel<<<dim3(128, 5), 256>>>(wq, wk, wv, wg, wo);

    {
        cudaFuncSetAttribute(proj_kernel, cudaFuncAttributeMaxDynamicSharedMemorySize, smem_proj);
        dim3 grid(HC / 64, NM / 128, 4);
        proj_kernel<<<grid, 256, smem_proj>>>(q_x, kv_x, bg);
    }
    {
        cudaFuncSetAttribute(attn_kernel, cudaFuncAttributeMaxDynamicSharedMemorySize, smem_attn);
        dim3 grid(NQ / 128, NB * NH);
        attn_kernel<<<grid, 256, smem_attn>>>(bias_mask, bias_pair);
    }
    {
        cudaFuncSetAttribute(out_kernel, cudaFuncAttributeMaxDynamicSharedMemorySize, smem_out);
        dim3 grid(ND / 64, NM / 64);
        out_kernel<<<grid, 256, smem_out>>>(bo, out);
    }
}

// round 13
// speedup vs baseline: 1.1145x; 1.1145x over previous
#include <cuda_runtime.h>
#include <cuda_bf16.h>
#include <math.h>
#include <stdint.h>

// Problem constants
#define NB 4
#define NQ 1024
#define NK 1024
#define ND 256
#define NH 8
#define NC 32
#define NM (NB*NQ)
#define HC (NH*NC)

#define QW 16              // words per row of packed q/k (32 channels / 2)

// Scratch (device globals)
__device__ uint32_t g_qph[NB*NH*NQ*QW];
__device__ uint32_t g_qpl[NB*NH*NQ*QW];
__device__ uint32_t g_kph[NB*NH*NK*QW];
__device__ uint32_t g_kpl[NB*NH*NK*QW];
__device__ float    g_v[NB*NH*NK*NC];
__device__ float    g_g[NM*HC];
__device__ float    g_o[NM*HC];
__device__ uint32_t g_wph[5*256*128];    // packed weights [mat][n][kw]
__device__ uint32_t g_wpl[5*256*128];

// ---------------------------------------------------------------------------
// helpers
// ---------------------------------------------------------------------------
__device__ __forceinline__ void bsplit2(float x0, float x1, uint32_t& h, uint32_t& l) {
    __nv_bfloat162 H = __floats2bfloat162_rn(x0, x1);
    float h0 = __low2float(H), h1 = __high2float(H);
    __nv_bfloat162 L = __floats2bfloat162_rn(x0 - h0, x1 - h1);
    h = *reinterpret_cast<uint32_t*>(&H);
    l = *reinterpret_cast<uint32_t*>(&L);
}
__device__ __forceinline__ void mma_bf16(float* d,
                                         uint32_t a0, uint32_t a1, uint32_t a2, uint32_t a3,
                                         uint32_t b0, uint32_t b1) {
    asm volatile(
        "mma.sync.aligned.m16n8k16.row.col.f32.bf16.bf16.f32 "
        "{%0,%1,%2,%3}, {%4,%5,%6,%7}, {%8,%9}, {%0,%1,%2,%3};\n"
        : "+f"(d[0]), "+f"(d[1]), "+f"(d[2]), "+f"(d[3])
        : "r"(a0), "r"(a1), "r"(a2), "r"(a3), "r"(b0), "r"(b1));
}
__device__ __forceinline__ uint32_t sptr(const void* p) {
    return (uint32_t)__cvta_generic_to_shared(p);
}
__device__ __forceinline__ void cp16(uint32_t s, const void* g) {
    asm volatile("cp.async.cg.shared.global [%0], [%1], 16;" :: "r"(s), "l"(g));
}
__device__ __forceinline__ void cp_commit() { asm volatile("cp.async.commit_group;"); }
__device__ __forceinline__ void cp_wait0()  { asm volatile("cp.async.wait_group 0;"); }
__device__ __forceinline__ void cp_wait1()  { asm volatile("cp.async.wait_group 1;"); }

extern __shared__ float smp[];

// ---------------------------------------------------------------------------
// Kernel 0: pack weights. grid=(128,5), 256.
// ---------------------------------------------------------------------------
__global__ __launch_bounds__(256) void pack_w_kernel(
    const float* __restrict__ wq, const float* __restrict__ wk,
    const float* __restrict__ wv, const float* __restrict__ wg,
    const float* __restrict__ wo)
{
    const int mat = blockIdx.y;
    const float* W = (mat == 0) ? wq : (mat == 1) ? wk : (mat == 2) ? wv :
                     (mat == 3) ? wg : wo;
    const int id = blockIdx.x * 256 + threadIdx.x;
    const int kw = id >> 8;
    const int n  = id & 255;
    float x0 = W[(2 * kw) * 256 + n];
    float x1 = W[(2 * kw + 1) * 256 + n];
    uint32_t h, l;
    bsplit2(x0, x1, h, l);
    g_wph[mat * 32768 + n * 128 + kw] = h;
    g_wpl[mat * 32768 + n * 128 + kw] = l;
}

// ---------------------------------------------------------------------------
// Kernel 1: projections. grid=(4, 32, 4), block=256. Tile 128M x 64N, k=32.
// Warp tile 32x32. mode: 0=q,1=k,2=v,3=gate
// ---------------------------------------------------------------------------
#define GST 20

__global__ __launch_bounds__(256, 2) void proj_kernel(
    const float* __restrict__ q_x, const float* __restrict__ kv_x,
    const float* __restrict__ bg)
{
    const int mode = blockIdx.z;
    const float* A = (mode == 1 || mode == 2) ? kv_x : q_x;
    const uint32_t* WPH = g_wph + mode * 32768;
    const uint32_t* WPL = g_wpl + mode * 32768;

    uint32_t* ah_s = (uint32_t*)smp;          // [128][GST]
    uint32_t* al_s = ah_s + 128 * GST;
    uint32_t* bh_s = al_s + 128 * GST;        // [64][GST]
    uint32_t* bl_s = bh_s + 64 * GST;

    const int tid  = threadIdx.x;
    const int lane = tid & 31;
    const int wid  = tid >> 5;
    const int gid  = lane >> 2;
    const int m4   = lane & 3;
    const int wm   = wid & 3;
    const int wn   = wid >> 2;
    const int m0   = blockIdx.y * 128;
    const int n0   = blockIdx.x * 64;

    float acc[2][4][4];
#pragma unroll
    for (int mt = 0; mt < 2; mt++)
#pragma unroll
        for (int nt = 0; nt < 4; nt++)
#pragma unroll
            for (int r = 0; r < 4; r++) acc[mt][nt][r] = 0.f;

    for (int k0 = 0; k0 < ND; k0 += 32) {
        __syncthreads();
#pragma unroll
        for (int u = 0; u < 4; u++) {
            const int e  = tid + 256 * u;
            const int r  = e >> 3;
            const int kw = (e & 7) * 2;
            float4 va = *(const float4*)(A + (size_t)(m0 + r) * ND + k0 + kw * 2);
            uint32_t h0, l0, h1, l1;
            bsplit2(va.x, va.y, h0, l0);
            bsplit2(va.z, va.w, h1, l1);
            *(uint2*)(ah_s + r * GST + kw) = make_uint2(h0, h1);
            *(uint2*)(al_s + r * GST + kw) = make_uint2(l0, l1);
        }
        {
            const int nl  = tid >> 2;
            const int kw4 = (tid & 3) * 4;
            *(uint4*)(bh_s + nl * GST + kw4) =
                *(const uint4*)(WPH + (size_t)(n0 + nl) * 128 + (k0 >> 1) + kw4);
            *(uint4*)(bl_s + nl * GST + kw4) =
                *(const uint4*)(WPL + (size_t)(n0 + nl) * 128 + (k0 >> 1) + kw4);
        }
        __syncthreads();

#pragma unroll
        for (int kc = 0; kc < 2; kc++) {
            uint32_t ah[2][4], al[2][4];
#pragma unroll
            for (int mt = 0; mt < 2; mt++) {
                const int rb = wm * 32 + mt * 16 + gid;
                ah[mt][0] = ah_s[(rb)     * GST + kc * 8 + m4];
                ah[mt][1] = ah_s[(rb + 8) * GST + kc * 8 + m4];
                ah[mt][2] = ah_s[(rb)     * GST + kc * 8 + m4 + 4];
                ah[mt][3] = ah_s[(rb + 8) * GST + kc * 8 + m4 + 4];
                al[mt][0] = al_s[(rb)     * GST + kc * 8 + m4];
                al[mt][1] = al_s[(rb + 8) * GST + kc * 8 + m4];
                al[mt][2] = al_s[(rb)     * GST + kc * 8 + m4 + 4];
                al[mt][3] = al_s[(rb + 8) * GST + kc * 8 + m4 + 4];
            }
#pragma unroll
            for (int nt = 0; nt < 4; nt++) {
                const int cb = wn * 32 + nt * 8 + gid;
                uint32_t bh0 = bh_s[cb * GST + kc * 8 + m4];
                uint32_t bh1 = bh_s[cb * GST + kc * 8 + m4 + 4];
                uint32_t bl0 = bl_s[cb * GST + kc * 8 + m4];
                uint32_t bl1 = bl_s[cb * GST + kc * 8 + m4 + 4];
#pragma unroll
                for (int mt = 0; mt < 2; mt++) {
                    mma_bf16(acc[mt][nt], ah[mt][0], ah[mt][1], ah[mt][2], ah[mt][3], bh0, bh1);
                    mma_bf16(acc[mt][nt], ah[mt][0], ah[mt][1], ah[mt][2], ah[mt][3], bl0, bl1);
                    mma_bf16(acc[mt][nt], al[mt][0], al[mt][1], al[mt][2], al[mt][3], bh0, bh1);
                }
            }
        }
    }

    const float qscale = 0.17677669529663687f;
#pragma unroll
    for (int mt = 0; mt < 2; mt++) {
#pragma unroll
        for (int rr = 0; rr < 2; rr++) {
            const int row = m0 + wm * 32 + mt * 16 + gid + rr * 8;
            const int b   = row >> 10;
            const int l   = row & 1023;
#pragma unroll
            for (int nt = 0; nt < 4; nt++) {
                const int n  = n0 + wn * 32 + nt * 8 + 2 * m4;
                const int h  = n >> 5;
                const int c  = n & 31;
                float v0 = acc[mt][nt][rr * 2 + 0];
                float v1 = acc[mt][nt][rr * 2 + 1];
                if (mode == 0) {
                    uint32_t hw, lw;
                    bsplit2(v0 * qscale, v1 * qscale, hw, lw);
                    const size_t wi = (((size_t)b * NH + h) * NQ + l) * QW + (c >> 1);
                    g_qph[wi] = hw; g_qpl[wi] = lw;
                } else if (mode == 1) {
                    uint32_t hw, lw;
                    bsplit2(v0, v1, hw, lw);
                    const size_t wi = (((size_t)b * NH + h) * NK + l) * QW + (c >> 1);
                    g_kph[wi] = hw; g_kpl[wi] = lw;
                } else if (mode == 2) {
                    *(float2*)(g_v + ((((size_t)b * NH + h) * NK) + l) * NC + c) = make_float2(v0, v1);
                } else {
                    float s0 = 1.f / (1.f + __expf(-(v0 + bg[n])));
                    float s1 = 1.f / (1.f + __expf(-(v1 + bg[n + 1])));
                    *(float2*)(g_g + (size_t)row * HC + n) = make_float2(s0, s1);
                }
            }
        }
    }
}

// ---------------------------------------------------------------------------
// Kernel 2: flash attention. hi/lo-interleaved K/V smem, register-resident P,
// bias_pair double-buffered via cp.async (one tile ahead).
// grid=(8, 32), block=256, 2 CTAs/SM.
// ---------------------------------------------------------------------------
#define K2ST 20   // K tile stride in uint2
#define V2ST 37   // V tile stride in uint2
#define BST  68   // bias tile stride in floats (64 + pad 4; 16B-aligned chunks)

__global__ __launch_bounds__(256, 2) void attn_kernel(
    const float* __restrict__ bias_mask,   // [B, K]
    const float* __restrict__ bias_pair)   // [B, H, Q, K]
{
    uint2* kv2 = (uint2*)smp;              // [64][K2ST] (hi,lo) pairs
    uint2* v2  = kv2 + 64 * K2ST;          // [32][V2ST]
    float* bms = (float*)(v2 + 32 * V2ST); // [64]
    float* bb0 = bms + 64;                 // bias tile buffer 0: [128][BST]
    float* bb1 = bb0 + 128 * BST;          // bias tile buffer 1
    float* bbuf[2] = { bb0, bb1 };

    const int tid  = threadIdx.x;
    const int lane = tid & 31;
    const int wid  = tid >> 5;
    const int gid  = lane >> 2;
    const int m4   = lane & 3;
    const int bh   = blockIdx.y;
    const int b    = bh >> 3;
    const int h    = bh & 7;
    const int q0   = blockIdx.x * 128;
    const int r0   = q0 + wid * 16 + gid;
    const int prow = wid * 16 + gid;

    // Q fragments (packed hi/lo words from gmem)
    uint32_t qh[2][4], ql[2][4];
    {
        const uint32_t* qbh = g_qph + (size_t)bh * NQ * QW;
        const uint32_t* qbl = g_qpl + (size_t)bh * NQ * QW;
#pragma unroll
        for (int kc = 0; kc < 2; kc++) {
            qh[kc][0] = qbh[(size_t)(r0)     * QW + kc * 8 + m4];
            qh[kc][1] = qbh[(size_t)(r0 + 8) * QW + kc * 8 + m4];
            qh[kc][2] = qbh[(size_t)(r0)     * QW + kc * 8 + m4 + 4];
            qh[kc][3] = qbh[(size_t)(r0 + 8) * QW + kc * 8 + m4 + 4];
            ql[kc][0] = qbl[(size_t)(r0)     * QW + kc * 8 + m4];
            ql[kc][1] = qbl[(size_t)(r0 + 8) * QW + kc * 8 + m4];
            ql[kc][2] = qbl[(size_t)(r0)     * QW + kc * 8 + m4 + 4];
            ql[kc][3] = qbl[(size_t)(r0 + 8) * QW + kc * 8 + m4 + 4];
        }
    }

    float m_i[2] = {-1e30f, -1e30f};
    float l_i[2] = {0.f, 0.f};
    float o[4][4];
#pragma unroll
    for (int nt = 0; nt < 4; nt++)
#pragma unroll
        for (int r = 0; r < 4; r++) o[nt][r] = 0.f;

    const uint32_t* kgh = g_kph + (size_t)bh * NK * QW;
    const uint32_t* kgl = g_kpl + (size_t)bh * NK * QW;
    const float*    vgb = g_v + (size_t)bh * NK * NC;
    const float*    bpq = bias_pair + ((size_t)bh * NQ + q0) * NK;  // tile rows base
    const float*    bmb = bias_mask + (size_t)b * NK;

    // bias tile staging: thread covers rows prow, prow+8; chunks ci = m4+4u
#define STAGE_BIAS(KT, BUF) do {                                              \
        const float* s1_ = bpq + (size_t)(prow)     * NK + (size_t)(KT) * 64; \
        const float* s2_ = bpq + (size_t)(prow + 8) * NK + (size_t)(KT) * 64; \
        float* d1_ = (BUF) + prow * BST;                                      \
        float* d2_ = (BUF) + (prow + 8) * BST;                                \
        _Pragma("unroll")                                                     \
        for (int u_ = 0; u_ < 4; u_++) {                                      \
            const int ci_ = (m4 + 4 * u_) * 4;                                \
            cp16(sptr(d1_ + ci_), s1_ + ci_);                                 \
            cp16(sptr(d2_ + ci_), s2_ + ci_);                                 \
        }                                                                     \
        cp_commit();                                                          \
    } while (0)

    // prologue: stage bias tile 0
    STAGE_BIAS(0, bbuf[0]);

    for (int kt = 0; kt < 16; kt++) {
        __syncthreads();   // previous iteration's smem readers done
        // issue next bias tile into the other buffer (consumed at kt+1)
        if (kt + 1 < 16) STAGE_BIAS(kt + 1, bbuf[(kt + 1) & 1]);

        // K tile: load hi/lo uint4 pairs, store interleaved (hi,lo) uint2s
        {
            const int r   = tid >> 2;
            const int kw4 = (tid & 3) * 4;
            const size_t src = ((size_t)(kt * 64 + r)) * QW + kw4;
            uint4 H = *(const uint4*)(kgh + src);
            uint4 L = *(const uint4*)(kgl + src);
            *(uint4*)(kv2 + r * K2ST + kw4)     = make_uint4(H.x, L.x, H.y, L.y);
            *(uint4*)(kv2 + r * K2ST + kw4 + 2) = make_uint4(H.z, L.z, H.w, L.w);
        }
        // V tile: fp32 -> kv-pair packed, interleaved (hi,lo)
        {
            const float* vg = vgb + (size_t)kt * 64 * NC;
#pragma unroll
            for (int u = 0; u < 4; u++) {
                const int w  = tid + 256 * u;
                const int c  = w & 31;
                const int r2 = w >> 5;
                float x0 = vg[(2 * r2)     * NC + c];
                float x1 = vg[(2 * r2 + 1) * NC + c];
                uint32_t hw, lw;
                bsplit2(x0, x1, hw, lw);
                v2[c * V2ST + r2] = make_uint2(hw, lw);
            }
            if (tid < 64) bms[tid] = bmb[kt * 64 + tid];
        }
        // current bias tile (group issued last iter) must be complete; the
        // tile-(kt+1) group just issued may remain in flight.
        if (kt + 1 < 16) cp_wait1(); else cp_wait0();
        __syncthreads();

        const float* bsm = bbuf[kt & 1];

        // S accumulators from smem-staged bias + bias_mask
        float s[8][4];
#pragma unroll
        for (int nt = 0; nt < 8; nt++) {
            const int c = nt * 8 + 2 * m4;
            const float bm0 = bms[c], bm1 = bms[c + 1];
            float2 p0 = *(const float2*)(bsm + prow * BST + c);
            float2 p1 = *(const float2*)(bsm + (prow + 8) * BST + c);
            s[nt][0] = p0.x + bm0; s[nt][1] = p0.y + bm1;
            s[nt][2] = p1.x + bm0; s[nt][3] = p1.y + bm1;
        }

        // S += Q @ K^T   (B-fragments via LDS.64: hi+lo in one fetch)
#pragma unroll
        for (int kc = 0; kc < 2; kc++) {
#pragma unroll
            for (int nt = 0; nt < 8; nt++) {
                const int cn = nt * 8 + gid;
                uint2 p0 = kv2[cn * K2ST + kc * 8 + m4];
                uint2 p1 = kv2[cn * K2ST + kc * 8 + m4 + 4];
                mma_bf16(s[nt], qh[kc][0], qh[kc][1], qh[kc][2], qh[kc][3], p0.x, p1.x);
                mma_bf16(s[nt], qh[kc][0], qh[kc][1], qh[kc][2], qh[kc][3], p0.y, p1.y);
                mma_bf16(s[nt], ql[kc][0], ql[kc][1], ql[kc][2], ql[kc][3], p0.x, p1.x);
            }
        }

        // online softmax (rows r0, r0+8); quad-local reduction
        float mx0 = -1e30f, mx1 = -1e30f;
#pragma unroll
        for (int nt = 0; nt < 8; nt++) {
            mx0 = fmaxf(mx0, fmaxf(s[nt][0], s[nt][1]));
            mx1 = fmaxf(mx1, fmaxf(s[nt][2], s[nt][3]));
        }
#pragma unroll
        for (int off = 1; off < 4; off <<= 1) {
            mx0 = fmaxf(mx0, __shfl_xor_sync(0xffffffffu, mx0, off));
            mx1 = fmaxf(mx1, __shfl_xor_sync(0xffffffffu, mx1, off));
        }
        const float mn0 = fmaxf(m_i[0], mx0);
        const float mn1 = fmaxf(m_i[1], mx1);
        const float al0 = __expf(m_i[0] - mn0);
        const float al1 = __expf(m_i[1] - mn1);
        float sum0 = 0.f, sum1 = 0.f;
#pragma unroll
        for (int nt = 0; nt < 8; nt++) {
            s[nt][0] = __expf(s[nt][0] - mn0);
            s[nt][1] = __expf(s[nt][1] - mn0);
            s[nt][2] = __expf(s[nt][2] - mn1);
            s[nt][3] = __expf(s[nt][3] - mn1);
            sum0 += s[nt][0] + s[nt][1];
            sum1 += s[nt][2] + s[nt][3];
        }
#pragma unroll
        for (int off = 1; off < 4; off <<= 1) {
            sum0 += __shfl_xor_sync(0xffffffffu, sum0, off);
            sum1 += __shfl_xor_sync(0xffffffffu, sum1, off);
        }
        l_i[0] = l_i[0] * al0 + sum0;
        l_i[1] = l_i[1] * al1 + sum1;
        m_i[0] = mn0; m_i[1] = mn1;
#pragma unroll
        for (int nt = 0; nt < 4; nt++) {
            o[nt][0] *= al0; o[nt][1] *= al0;
            o[nt][2] *= al1; o[nt][3] *= al1;
        }

        // O += P @ V — register-resident P (S C-fragment layout == PV A-fragment)
#pragma unroll
        for (int kc = 0; kc < 4; kc++) {
            uint32_t a0h, a0l, a1h, a1l, a2h, a2l, a3h, a3l;
            bsplit2(s[2*kc][0],   s[2*kc][1],   a0h, a0l);
            bsplit2(s[2*kc][2],   s[2*kc][3],   a1h, a1l);
            bsplit2(s[2*kc+1][0], s[2*kc+1][1], a2h, a2l);
            bsplit2(s[2*kc+1][2], s[2*kc+1][3], a3h, a3l);
#pragma unroll
            for (int nt = 0; nt < 4; nt++) {
                const int cn = nt * 8 + gid;
                uint2 p0 = v2[cn * V2ST + kc * 8 + m4];
                uint2 p1 = v2[cn * V2ST + kc * 8 + m4 + 4];
                mma_bf16(o[nt], a0h, a1h, a2h, a3h, p0.x, p1.x);
                mma_bf16(o[nt], a0h, a1h, a2h, a3h, p0.y, p1.y);
                mma_bf16(o[nt], a0l, a1l, a2l, a3l, p0.x, p1.x);
            }
        }
    }
#undef STAGE_BIAS

    // epilogue: normalize, write [B, Q, H, C]
    const float inv0 = 1.f / l_i[0];
    const float inv1 = 1.f / l_i[1];
#pragma unroll
    for (int nt = 0; nt < 4; nt++) {
        const int c = nt * 8 + 2 * m4;
        *(float2*)(g_o + (((size_t)b * NQ + r0)     * NH + h) * NC + c) =
            make_float2(o[nt][0] * inv0, o[nt][1] * inv0);
        *(float2*)(g_o + (((size_t)b * NQ + r0 + 8) * NH + h) * NC + c) =
            make_float2(o[nt][2] * inv1, o[nt][3] * inv1);
    }
}

// ---------------------------------------------------------------------------
// Kernel 3: out = (o * g) @ wo + bo. grid=(4, 64), block=256. Tile 64x64.
// ---------------------------------------------------------------------------
__global__ __launch_bounds__(256, 2) void out_kernel(
    const float* __restrict__ bo, float* __restrict__ out)
{
    const uint32_t* WPH = g_wph + 4 * 32768;
    const uint32_t* WPL = g_wpl + 4 * 32768;

    uint32_t* ah_s = (uint32_t*)smp;          // [64][GST]
    uint32_t* al_s = ah_s + 64 * GST;
    uint32_t* bh_s = al_s + 64 * GST;         // [64][GST]
    uint32_t* bl_s = bh_s + 64 * GST;

    const int tid  = threadIdx.x;
    const int lane = tid & 31;
    const int wid  = tid >> 5;
    const int gid  = lane >> 2;
    const int m4   = lane & 3;
    const int wm   = wid & 1;
    const int wn   = wid >> 1;
    const int m0   = blockIdx.y * 64;
    const int n0   = blockIdx.x * 64;

    float acc[2][2][4];
#pragma unroll
    for (int mt = 0; mt < 2; mt++)
#pragma unroll
        for (int nt = 0; nt < 2; nt++)
#pragma unroll
            for (int r = 0; r < 4; r++) acc[mt][nt][r] = 0.f;

    for (int k0 = 0; k0 < HC; k0 += 32) {
        __syncthreads();
#pragma unroll
        for (int u = 0; u < 2; u++) {
            const int e  = tid + 256 * u;
            const int r  = e >> 3;
            const int kw = (e & 7) * 2;
            const size_t idx = (size_t)(m0 + r) * HC + k0 + kw * 2;
            float4 va = *(const float4*)(g_o + idx);
            float4 vg = *(const float4*)(g_g + idx);
            va.x *= vg.x; va.y *= vg.y; va.z *= vg.z; va.w *= vg.w;
            uint32_t h0, l0, h1, l1;
            bsplit2(va.x, va.y, h0, l0);
            bsplit2(va.z, va.w, h1, l1);
            *(uint2*)(ah_s + r * GST + kw) = make_uint2(h0, h1);
            *(uint2*)(al_s + r * GST + kw) = make_uint2(l0, l1);
        }
        {
            const int nl  = tid >> 2;
            const int kw4 = (tid & 3) * 4;
            *(uint4*)(bh_s + nl * GST + kw4) =
                *(const uint4*)(WPH + (size_t)(n0 + nl) * 128 + (k0 >> 1) + kw4);
            *(uint4*)(bl_s + nl * GST + kw4) =
                *(const uint4*)(WPL + (size_t)(n0 + nl) * 128 + (k0 >> 1) + kw4);
        }
        __syncthreads();

#pragma unroll
        for (int kc = 0; kc < 2; kc++) {
            uint32_t ah[2][4], al[2][4];
#pragma unroll
            for (int mt = 0; mt < 2; mt++) {
                const int rb = wm * 32 + mt * 16 + gid;
                ah[mt][0] = ah_s[(rb)     * GST + kc * 8 + m4];
                ah[mt][1] = ah_s[(rb + 8) * GST + kc * 8 + m4];
                ah[mt][2] = ah_s[(rb)     * GST + kc * 8 + m4 + 4];
                ah[mt][3] = ah_s[(rb + 8) * GST + kc * 8 + m4 + 4];
                al[mt][0] = al_s[(rb)     * GST + kc * 8 + m4];
                al[mt][1] = al_s[(rb + 8) * GST + kc * 8 + m4];
                al[mt][2] = al_s[(rb)     * GST + kc * 8 + m4 + 4];
                al[mt][3] = al_s[(rb + 8) * GST + kc * 8 + m4 + 4];
            }
#pragma unroll
            for (int nt = 0; nt < 2; nt++) {
                const int cb = wn * 16 + nt * 8 + gid;
                uint32_t bh0 = bh_s[cb * GST + kc * 8 + m4];
                uint32_t bh1 = bh_s[cb * GST + kc * 8 + m4 + 4];
                uint32_t bl0 = bl_s[cb * GST + kc * 8 + m4];
                uint32_t bl1 = bl_s[cb * GST + kc * 8 + m4 + 4];
#pragma unroll
                for (int mt = 0; mt < 2; mt++) {
                    mma_bf16(acc[mt][nt], ah[mt][0], ah[mt][1], ah[mt][2], ah[mt][3], bh0, bh1);
                    mma_bf16(acc[mt][nt], ah[mt][0], ah[mt][1], ah[mt][2], ah[mt][3], bl0, bl1);
                    mma_bf16(acc[mt][nt], al[mt][0], al[mt][1], al[mt][2], al[mt][3], bh0, bh1);
                }
            }
        }
    }

#pragma unroll
    for (int mt = 0; mt < 2; mt++) {
#pragma unroll
        for (int rr = 0; rr < 2; rr++) {
            const int row = m0 + wm * 32 + mt * 16 + gid + rr * 8;
#pragma unroll
            for (int nt = 0; nt < 2; nt++) {
                const int n = n0 + wn * 16 + nt * 8 + 2 * m4;
                float v0 = acc[mt][nt][rr * 2 + 0] + bo[n];
                float v1 = acc[mt][nt][rr * 2 + 1] + bo[n + 1];
                *(float2*)(out + (size_t)row * ND + n) = make_float2(v0, v1);
            }
        }
    }
}

// ---------------------------------------------------------------------------
// Launch
// ---------------------------------------------------------------------------
extern "C" void kernel_launch(void* const* d_in, const int* in_sizes, int n_in,
                              void* d_out, int out_size)
{
    const float* q_x       = (const float*)d_in[0];
    const float* kv_x      = (const float*)d_in[1];
    const float* bias_mask = (const float*)d_in[2];
    const float* bias_pair = (const float*)d_in[3];
    const float* wq        = (const float*)d_in[4];
    const float* wk        = (const float*)d_in[5];
    const float* wv        = (const float*)d_in[6];
    const float* wg        = (const float*)d_in[7];
    const float* bg        = (const float*)d_in[8];
    const float* wo        = (const float*)d_in[9];
    const float* bo        = (const float*)d_in[10];
    float* out             = (float*)d_out;

    const int smem_proj = (2 * 128 + 2 * 64) * GST * (int)sizeof(uint32_t);   // 30720
    const int smem_attn = (64 * K2ST + 32 * V2ST) * (int)sizeof(uint2)
                          + 64 * (int)sizeof(float)
                          + 2 * 128 * BST * (int)sizeof(float);                // 89600
    const int smem_out  = 4 * 64 * GST * (int)sizeof(uint32_t);               // 20480

    pack_w_kernel<<<dim3(128, 5), 256>>>(wq, wk, wv, wg, wo);

    {
        cudaFuncSetAttribute(proj_kernel, cudaFuncAttributeMaxDynamicSharedMemorySize, smem_proj);
        dim3 grid(HC / 64, NM / 128, 4);
        proj_kernel<<<grid, 256, smem_proj>>>(q_x, kv_x, bg);
    }
    {
        cudaFuncSetAttribute(attn_kernel, cudaFuncAttributeMaxDynamicSharedMemorySize, smem_attn);
        dim3 grid(NQ / 128, NB * NH);
        attn_kernel<<<grid, 256, smem_attn>>>(bias_mask, bias_pair);
    }
    {
        cudaFuncSetAttribute(out_kernel, cudaFuncAttributeMaxDynamicSharedMemorySize, smem_out);
        dim3 grid(ND / 64, NM / 64);
        out_kernel<<<grid, 256, smem_out>>>(bo, out);
    }
}

// round 14
// speedup vs baseline: 1.1285x; 1.0126x over previous
#include <cuda_runtime.h>
#include <cuda_bf16.h>
#include <math.h>
#include <stdint.h>

// Problem constants
#define NB 4
#define NQ 1024
#define NK 1024
#define ND 256
#define NH 8
#define NC 32
#define NM (NB*NQ)
#define HC (NH*NC)

#define QW 16              // words per row of packed q/k (32 channels / 2)

// Scratch (device globals)
__device__ uint32_t g_qph[NB*NH*NQ*QW];
__device__ uint32_t g_qpl[NB*NH*NQ*QW];
__device__ uint32_t g_kph[NB*NH*NK*QW];
__device__ uint32_t g_kpl[NB*NH*NK*QW];
__device__ float    g_v[NB*NH*NK*NC];
__device__ float    g_g[NM*HC];
__device__ float    g_o[NM*HC];
__device__ uint32_t g_wph[5*256*128];    // packed weights [mat][n][kw]
__device__ uint32_t g_wpl[5*256*128];

// ---------------------------------------------------------------------------
// helpers
// ---------------------------------------------------------------------------
__device__ __forceinline__ void bsplit2(float x0, float x1, uint32_t& h, uint32_t& l) {
    __nv_bfloat162 H = __floats2bfloat162_rn(x0, x1);
    float h0 = __low2float(H), h1 = __high2float(H);
    __nv_bfloat162 L = __floats2bfloat162_rn(x0 - h0, x1 - h1);
    h = *reinterpret_cast<uint32_t*>(&H);
    l = *reinterpret_cast<uint32_t*>(&L);
}
__device__ __forceinline__ void mma_bf16(float* d,
                                         uint32_t a0, uint32_t a1, uint32_t a2, uint32_t a3,
                                         uint32_t b0, uint32_t b1) {
    asm volatile(
        "mma.sync.aligned.m16n8k16.row.col.f32.bf16.bf16.f32 "
        "{%0,%1,%2,%3}, {%4,%5,%6,%7}, {%8,%9}, {%0,%1,%2,%3};\n"
        : "+f"(d[0]), "+f"(d[1]), "+f"(d[2]), "+f"(d[3])
        : "r"(a0), "r"(a1), "r"(a2), "r"(a3), "r"(b0), "r"(b1));
}
__device__ __forceinline__ uint32_t sptr(const void* p) {
    return (uint32_t)__cvta_generic_to_shared(p);
}
__device__ __forceinline__ void cp16(uint32_t s, const void* g) {
    asm volatile("cp.async.cg.shared.global [%0], [%1], 16;" :: "r"(s), "l"(g));
}
__device__ __forceinline__ void cp_commit() { asm volatile("cp.async.commit_group;"); }
__device__ __forceinline__ void cp_wait0()  { asm volatile("cp.async.wait_group 0;"); }
__device__ __forceinline__ void cp_wait1()  { asm volatile("cp.async.wait_group 1;"); }

extern __shared__ float smp[];

// ---------------------------------------------------------------------------
// Kernel 0: pack weights. grid=(128,5), 256.
// ---------------------------------------------------------------------------
__global__ __launch_bounds__(256) void pack_w_kernel(
    const float* __restrict__ wq, const float* __restrict__ wk,
    const float* __restrict__ wv, const float* __restrict__ wg,
    const float* __restrict__ wo)
{
    const int mat = blockIdx.y;
    const float* W = (mat == 0) ? wq : (mat == 1) ? wk : (mat == 2) ? wv :
                     (mat == 3) ? wg : wo;
    const int id = blockIdx.x * 256 + threadIdx.x;
    const int kw = id >> 8;
    const int n  = id & 255;
    float x0 = W[(2 * kw) * 256 + n];
    float x1 = W[(2 * kw + 1) * 256 + n];
    uint32_t h, l;
    bsplit2(x0, x1, h, l);
    g_wph[mat * 32768 + n * 128 + kw] = h;
    g_wpl[mat * 32768 + n * 128 + kw] = l;
}

// ---------------------------------------------------------------------------
// Kernel 1: projections, software-pipelined k-loop. grid=(4, 32, 4), block=256.
// Tile 128M x 64N, k=32. A via register prefetch; B via cp.async double buffer.
// mode: 0=q,1=k,2=v,3=gate
// ---------------------------------------------------------------------------
#define GST 20

__global__ __launch_bounds__(256, 2) void proj_kernel(
    const float* __restrict__ q_x, const float* __restrict__ kv_x,
    const float* __restrict__ bg)
{
    const int mode = blockIdx.z;
    const float* A = (mode == 1 || mode == 2) ? kv_x : q_x;
    const uint32_t* WPH = g_wph + mode * 32768;
    const uint32_t* WPL = g_wpl + mode * 32768;

    uint32_t* ah_s = (uint32_t*)smp;          // [128][GST]
    uint32_t* al_s = ah_s + 128 * GST;
    uint32_t* bbh[2]; uint32_t* bbl[2];
    bbh[0] = al_s + 128 * GST;                // [64][GST] each
    bbl[0] = bbh[0] + 64 * GST;
    bbh[1] = bbl[0] + 64 * GST;
    bbl[1] = bbh[1] + 64 * GST;

    const int tid  = threadIdx.x;
    const int lane = tid & 31;
    const int wid  = tid >> 5;
    const int gid  = lane >> 2;
    const int m4   = lane & 3;
    const int wm   = wid & 3;
    const int wn   = wid >> 2;
    const int m0   = blockIdx.y * 128;
    const int n0   = blockIdx.x * 64;

    const int bnl  = tid >> 2;
    const int bkw4 = (tid & 3) * 4;

    float acc[2][4][4];
#pragma unroll
    for (int mt = 0; mt < 2; mt++)
#pragma unroll
        for (int nt = 0; nt < 4; nt++)
#pragma unroll
            for (int r = 0; r < 4; r++) acc[mt][nt][r] = 0.f;

    // prologue: A tile 0 into registers, B tile 0 via cp.async
    float4 aReg[4];
#pragma unroll
    for (int u = 0; u < 4; u++) {
        const int e  = tid + 256 * u;
        const int r  = e >> 3;
        const int kw = (e & 7) * 2;
        aReg[u] = *(const float4*)(A + (size_t)(m0 + r) * ND + kw * 2);
    }
    cp16(sptr(bbh[0] + bnl * GST + bkw4), WPH + (size_t)(n0 + bnl) * 128 + bkw4);
    cp16(sptr(bbl[0] + bnl * GST + bkw4), WPL + (size_t)(n0 + bnl) * 128 + bkw4);
    cp_commit();

    for (int ki = 0; ki < 8; ki++) {
        __syncthreads();     // prior compute done reading A smem / B buffer
        // store current A tile (convert)
#pragma unroll
        for (int u = 0; u < 4; u++) {
            const int e  = tid + 256 * u;
            const int r  = e >> 3;
            const int kw = (e & 7) * 2;
            uint32_t h0, l0, h1, l1;
            bsplit2(aReg[u].x, aReg[u].y, h0, l0);
            bsplit2(aReg[u].z, aReg[u].w, h1, l1);
            *(uint2*)(ah_s + r * GST + kw) = make_uint2(h0, h1);
            *(uint2*)(al_s + r * GST + kw) = make_uint2(l0, l1);
        }
        // prefetch next tile: A -> regs (LDG in flight), B -> cp.async
        if (ki + 1 < 8) {
            const int k0n = (ki + 1) * 32;
#pragma unroll
            for (int u = 0; u < 4; u++) {
                const int e  = tid + 256 * u;
                const int r  = e >> 3;
                const int kw = (e & 7) * 2;
                aReg[u] = *(const float4*)(A + (size_t)(m0 + r) * ND + k0n + kw * 2);
            }
            uint32_t* dh = bbh[(ki + 1) & 1];
            uint32_t* dl = bbl[(ki + 1) & 1];
            cp16(sptr(dh + bnl * GST + bkw4),
                 WPH + (size_t)(n0 + bnl) * 128 + (k0n >> 1) + bkw4);
            cp16(sptr(dl + bnl * GST + bkw4),
                 WPL + (size_t)(n0 + bnl) * 128 + (k0n >> 1) + bkw4);
            cp_commit();
            cp_wait1();      // current B tile complete; next stays in flight
        } else {
            cp_wait0();
        }
        __syncthreads();

        const uint32_t* bh_s = bbh[ki & 1];
        const uint32_t* bl_s = bbl[ki & 1];

#pragma unroll
        for (int kc = 0; kc < 2; kc++) {
            uint32_t ah[2][4], al[2][4];
#pragma unroll
            for (int mt = 0; mt < 2; mt++) {
                const int rb = wm * 32 + mt * 16 + gid;
                ah[mt][0] = ah_s[(rb)     * GST + kc * 8 + m4];
                ah[mt][1] = ah_s[(rb + 8) * GST + kc * 8 + m4];
                ah[mt][2] = ah_s[(rb)     * GST + kc * 8 + m4 + 4];
                ah[mt][3] = ah_s[(rb + 8) * GST + kc * 8 + m4 + 4];
                al[mt][0] = al_s[(rb)     * GST + kc * 8 + m4];
                al[mt][1] = al_s[(rb + 8) * GST + kc * 8 + m4];
                al[mt][2] = al_s[(rb)     * GST + kc * 8 + m4 + 4];
                al[mt][3] = al_s[(rb + 8) * GST + kc * 8 + m4 + 4];
            }
#pragma unroll
            for (int nt = 0; nt < 4; nt++) {
                const int cb = wn * 32 + nt * 8 + gid;
                uint32_t bh0 = bh_s[cb * GST + kc * 8 + m4];
                uint32_t bh1 = bh_s[cb * GST + kc * 8 + m4 + 4];
                uint32_t bl0 = bl_s[cb * GST + kc * 8 + m4];
                uint32_t bl1 = bl_s[cb * GST + kc * 8 + m4 + 4];
#pragma unroll
                for (int mt = 0; mt < 2; mt++) {
                    mma_bf16(acc[mt][nt], ah[mt][0], ah[mt][1], ah[mt][2], ah[mt][3], bh0, bh1);
                    mma_bf16(acc[mt][nt], ah[mt][0], ah[mt][1], ah[mt][2], ah[mt][3], bl0, bl1);
                    mma_bf16(acc[mt][nt], al[mt][0], al[mt][1], al[mt][2], al[mt][3], bh0, bh1);
                }
            }
        }
    }

    const float qscale = 0.17677669529663687f;
#pragma unroll
    for (int mt = 0; mt < 2; mt++) {
#pragma unroll
        for (int rr = 0; rr < 2; rr++) {
            const int row = m0 + wm * 32 + mt * 16 + gid + rr * 8;
            const int b   = row >> 10;
            const int l   = row & 1023;
#pragma unroll
            for (int nt = 0; nt < 4; nt++) {
                const int n  = n0 + wn * 32 + nt * 8 + 2 * m4;
                const int h  = n >> 5;
                const int c  = n & 31;
                float v0 = acc[mt][nt][rr * 2 + 0];
                float v1 = acc[mt][nt][rr * 2 + 1];
                if (mode == 0) {
                    uint32_t hw, lw;
                    bsplit2(v0 * qscale, v1 * qscale, hw, lw);
                    const size_t wi = (((size_t)b * NH + h) * NQ + l) * QW + (c >> 1);
                    g_qph[wi] = hw; g_qpl[wi] = lw;
                } else if (mode == 1) {
                    uint32_t hw, lw;
                    bsplit2(v0, v1, hw, lw);
                    const size_t wi = (((size_t)b * NH + h) * NK + l) * QW + (c >> 1);
                    g_kph[wi] = hw; g_kpl[wi] = lw;
                } else if (mode == 2) {
                    *(float2*)(g_v + ((((size_t)b * NH + h) * NK) + l) * NC + c) = make_float2(v0, v1);
                } else {
                    float s0 = 1.f / (1.f + __expf(-(v0 + bg[n])));
                    float s1 = 1.f / (1.f + __expf(-(v1 + bg[n + 1])));
                    *(float2*)(g_g + (size_t)row * HC + n) = make_float2(s0, s1);
                }
            }
        }
    }
}

// ---------------------------------------------------------------------------
// Kernel 2: flash attention (R13 state: hi/lo-interleaved K/V, register P,
// cp.async double-buffered bias_pair). grid=(8, 32), block=256, 2 CTAs/SM.
// ---------------------------------------------------------------------------
#define K2ST 20   // K tile stride in uint2
#define V2ST 37   // V tile stride in uint2
#define BST  68   // bias tile stride in floats

__global__ __launch_bounds__(256, 2) void attn_kernel(
    const float* __restrict__ bias_mask,   // [B, K]
    const float* __restrict__ bias_pair)   // [B, H, Q, K]
{
    uint2* kv2 = (uint2*)smp;              // [64][K2ST]
    uint2* v2  = kv2 + 64 * K2ST;          // [32][V2ST]
    float* bms = (float*)(v2 + 32 * V2ST); // [64]
    float* bb0 = bms + 64;                 // [128][BST]
    float* bb1 = bb0 + 128 * BST;
    float* bbuf[2] = { bb0, bb1 };

    const int tid  = threadIdx.x;
    const int lane = tid & 31;
    const int wid  = tid >> 5;
    const int gid  = lane >> 2;
    const int m4   = lane & 3;
    const int bh   = blockIdx.y;
    const int b    = bh >> 3;
    const int h    = bh & 7;
    const int q0   = blockIdx.x * 128;
    const int r0   = q0 + wid * 16 + gid;
    const int prow = wid * 16 + gid;

    uint32_t qh[2][4], ql[2][4];
    {
        const uint32_t* qbh = g_qph + (size_t)bh * NQ * QW;
        const uint32_t* qbl = g_qpl + (size_t)bh * NQ * QW;
#pragma unroll
        for (int kc = 0; kc < 2; kc++) {
            qh[kc][0] = qbh[(size_t)(r0)     * QW + kc * 8 + m4];
            qh[kc][1] = qbh[(size_t)(r0 + 8) * QW + kc * 8 + m4];
            qh[kc][2] = qbh[(size_t)(r0)     * QW + kc * 8 + m4 + 4];
            qh[kc][3] = qbh[(size_t)(r0 + 8) * QW + kc * 8 + m4 + 4];
            ql[kc][0] = qbl[(size_t)(r0)     * QW + kc * 8 + m4];
            ql[kc][1] = qbl[(size_t)(r0 + 8) * QW + kc * 8 + m4];
            ql[kc][2] = qbl[(size_t)(r0)     * QW + kc * 8 + m4 + 4];
            ql[kc][3] = qbl[(size_t)(r0 + 8) * QW + kc * 8 + m4 + 4];
        }
    }

    float m_i[2] = {-1e30f, -1e30f};
    float l_i[2] = {0.f, 0.f};
    float o[4][4];
#pragma unroll
    for (int nt = 0; nt < 4; nt++)
#pragma unroll
        for (int r = 0; r < 4; r++) o[nt][r] = 0.f;

    const uint32_t* kgh = g_kph + (size_t)bh * NK * QW;
    const uint32_t* kgl = g_kpl + (size_t)bh * NK * QW;
    const float*    vgb = g_v + (size_t)bh * NK * NC;
    const float*    bpq = bias_pair + ((size_t)bh * NQ + q0) * NK;
    const float*    bmb = bias_mask + (size_t)b * NK;

#define STAGE_BIAS(KT, BUF) do {                                              \
        const float* s1_ = bpq + (size_t)(prow)     * NK + (size_t)(KT) * 64; \
        const float* s2_ = bpq + (size_t)(prow + 8) * NK + (size_t)(KT) * 64; \
        float* d1_ = (BUF) + prow * BST;                                      \
        float* d2_ = (BUF) + (prow + 8) * BST;                                \
        _Pragma("unroll")                                                     \
        for (int u_ = 0; u_ < 4; u_++) {                                      \
            const int ci_ = (m4 + 4 * u_) * 4;                                \
            cp16(sptr(d1_ + ci_), s1_ + ci_);                                 \
            cp16(sptr(d2_ + ci_), s2_ + ci_);                                 \
        }                                                                     \
        cp_commit();                                                          \
    } while (0)

    STAGE_BIAS(0, bbuf[0]);

    for (int kt = 0; kt < 16; kt++) {
        __syncthreads();
        if (kt + 1 < 16) STAGE_BIAS(kt + 1, bbuf[(kt + 1) & 1]);

        {
            const int r   = tid >> 2;
            const int kw4 = (tid & 3) * 4;
            const size_t src = ((size_t)(kt * 64 + r)) * QW + kw4;
            uint4 H = *(const uint4*)(kgh + src);
            uint4 L = *(const uint4*)(kgl + src);
            *(uint4*)(kv2 + r * K2ST + kw4)     = make_uint4(H.x, L.x, H.y, L.y);
            *(uint4*)(kv2 + r * K2ST + kw4 + 2) = make_uint4(H.z, L.z, H.w, L.w);
        }
        {
            const float* vg = vgb + (size_t)kt * 64 * NC;
#pragma unroll
            for (int u = 0; u < 4; u++) {
                const int w  = tid + 256 * u;
                const int c  = w & 31;
                const int r2 = w >> 5;
                float x0 = vg[(2 * r2)     * NC + c];
                float x1 = vg[(2 * r2 + 1) * NC + c];
                uint32_t hw, lw;
                bsplit2(x0, x1, hw, lw);
                v2[c * V2ST + r2] = make_uint2(hw, lw);
            }
            if (tid < 64) bms[tid] = bmb[kt * 64 + tid];
        }
        if (kt + 1 < 16) cp_wait1(); else cp_wait0();
        __syncthreads();

        const float* bsm = bbuf[kt & 1];

        float s[8][4];
#pragma unroll
        for (int nt = 0; nt < 8; nt++) {
            const int c = nt * 8 + 2 * m4;
            const float bm0 = bms[c], bm1 = bms[c + 1];
            float2 p0 = *(const float2*)(bsm + prow * BST + c);
            float2 p1 = *(const float2*)(bsm + (prow + 8) * BST + c);
            s[nt][0] = p0.x + bm0; s[nt][1] = p0.y + bm1;
            s[nt][2] = p1.x + bm0; s[nt][3] = p1.y + bm1;
        }

#pragma unroll
        for (int kc = 0; kc < 2; kc++) {
#pragma unroll
            for (int nt = 0; nt < 8; nt++) {
                const int cn = nt * 8 + gid;
                uint2 p0 = kv2[cn * K2ST + kc * 8 + m4];
                uint2 p1 = kv2[cn * K2ST + kc * 8 + m4 + 4];
                mma_bf16(s[nt], qh[kc][0], qh[kc][1], qh[kc][2], qh[kc][3], p0.x, p1.x);
                mma_bf16(s[nt], qh[kc][0], qh[kc][1], qh[kc][2], qh[kc][3], p0.y, p1.y);
                mma_bf16(s[nt], ql[kc][0], ql[kc][1], ql[kc][2], ql[kc][3], p0.x, p1.x);
            }
        }

        float mx0 = -1e30f, mx1 = -1e30f;
#pragma unroll
        for (int nt = 0; nt < 8; nt++) {
            mx0 = fmaxf(mx0, fmaxf(s[nt][0], s[nt][1]));
            mx1 = fmaxf(mx1, fmaxf(s[nt][2], s[nt][3]));
        }
#pragma unroll
        for (int off = 1; off < 4; off <<= 1) {
            mx0 = fmaxf(mx0, __shfl_xor_sync(0xffffffffu, mx0, off));
            mx1 = fmaxf(mx1, __shfl_xor_sync(0xffffffffu, mx1, off));
        }
        const float mn0 = fmaxf(m_i[0], mx0);
        const float mn1 = fmaxf(m_i[1], mx1);
        const float al0 = __expf(m_i[0] - mn0);
        const float al1 = __expf(m_i[1] - mn1);
        float sum0 = 0.f, sum1 = 0.f;
#pragma unroll
        for (int nt = 0; nt < 8; nt++) {
            s[nt][0] = __expf(s[nt][0] - mn0);
            s[nt][1] = __expf(s[nt][1] - mn0);
            s[nt][2] = __expf(s[nt][2] - mn1);
            s[nt][3] = __expf(s[nt][3] - mn1);
            sum0 += s[nt][0] + s[nt][1];
            sum1 += s[nt][2] + s[nt][3];
        }
#pragma unroll
        for (int off = 1; off < 4; off <<= 1) {
            sum0 += __shfl_xor_sync(0xffffffffu, sum0, off);
            sum1 += __shfl_xor_sync(0xffffffffu, sum1, off);
        }
        l_i[0] = l_i[0] * al0 + sum0;
        l_i[1] = l_i[1] * al1 + sum1;
        m_i[0] = mn0; m_i[1] = mn1;
#pragma unroll
        for (int nt = 0; nt < 4; nt++) {
            o[nt][0] *= al0; o[nt][1] *= al0;
            o[nt][2] *= al1; o[nt][3] *= al1;
        }

#pragma unroll
        for (int kc = 0; kc < 4; kc++) {
            uint32_t a0h, a0l, a1h, a1l, a2h, a2l, a3h, a3l;
            bsplit2(s[2*kc][0],   s[2*kc][1],   a0h, a0l);
            bsplit2(s[2*kc][2],   s[2*kc][3],   a1h, a1l);
            bsplit2(s[2*kc+1][0], s[2*kc+1][1], a2h, a2l);
            bsplit2(s[2*kc+1][2], s[2*kc+1][3], a3h, a3l);
#pragma unroll
            for (int nt = 0; nt < 4; nt++) {
                const int cn = nt * 8 + gid;
                uint2 p0 = v2[cn * V2ST + kc * 8 + m4];
                uint2 p1 = v2[cn * V2ST + kc * 8 + m4 + 4];
                mma_bf16(o[nt], a0h, a1h, a2h, a3h, p0.x, p1.x);
                mma_bf16(o[nt], a0h, a1h, a2h, a3h, p0.y, p1.y);
                mma_bf16(o[nt], a0l, a1l, a2l, a3l, p0.x, p1.x);
            }
        }
    }
#undef STAGE_BIAS

    const float inv0 = 1.f / l_i[0];
    const float inv1 = 1.f / l_i[1];
#pragma unroll
    for (int nt = 0; nt < 4; nt++) {
        const int c = nt * 8 + 2 * m4;
        *(float2*)(g_o + (((size_t)b * NQ + r0)     * NH + h) * NC + c) =
            make_float2(o[nt][0] * inv0, o[nt][1] * inv0);
        *(float2*)(g_o + (((size_t)b * NQ + r0 + 8) * NH + h) * NC + c) =
            make_float2(o[nt][2] * inv1, o[nt][3] * inv1);
    }
}

// ---------------------------------------------------------------------------
// Kernel 3: out = (o * g) @ wo + bo, software-pipelined k-loop.
// grid=(4, 64), block=256. Tile 64x64.
// ---------------------------------------------------------------------------
__global__ __launch_bounds__(256, 2) void out_kernel(
    const float* __restrict__ bo, float* __restrict__ out)
{
    const uint32_t* WPH = g_wph + 4 * 32768;
    const uint32_t* WPL = g_wpl + 4 * 32768;

    uint32_t* ah_s = (uint32_t*)smp;          // [64][GST]
    uint32_t* al_s = ah_s + 64 * GST;
    uint32_t* bbh[2]; uint32_t* bbl[2];
    bbh[0] = al_s + 64 * GST;
    bbl[0] = bbh[0] + 64 * GST;
    bbh[1] = bbl[0] + 64 * GST;
    bbl[1] = bbh[1] + 64 * GST;

    const int tid  = threadIdx.x;
    const int lane = tid & 31;
    const int wid  = tid >> 5;
    const int gid  = lane >> 2;
    const int m4   = lane & 3;
    const int wm   = wid & 1;
    const int wn   = wid >> 1;
    const int m0   = blockIdx.y * 64;
    const int n0   = blockIdx.x * 64;

    const int bnl  = tid >> 2;
    const int bkw4 = (tid & 3) * 4;

    float acc[2][2][4];
#pragma unroll
    for (int mt = 0; mt < 2; mt++)
#pragma unroll
        for (int nt = 0; nt < 2; nt++)
#pragma unroll
            for (int r = 0; r < 4; r++) acc[mt][nt][r] = 0.f;

    // prologue: A tile 0 regs (o and g), B tile 0 cp.async
    float4 aR[2], gR[2];
#pragma unroll
    for (int u = 0; u < 2; u++) {
        const int e  = tid + 256 * u;
        const int r  = e >> 3;
        const int kw = (e & 7) * 2;
        const size_t idx = (size_t)(m0 + r) * HC + kw * 2;
        aR[u] = *(const float4*)(g_o + idx);
        gR[u] = *(const float4*)(g_g + idx);
    }
    cp16(sptr(bbh[0] + bnl * GST + bkw4), WPH + (size_t)(n0 + bnl) * 128 + bkw4);
    cp16(sptr(bbl[0] + bnl * GST + bkw4), WPL + (size_t)(n0 + bnl) * 128 + bkw4);
    cp_commit();

    for (int ki = 0; ki < 8; ki++) {
        __syncthreads();
        // store current A tile (gate + convert)
#pragma unroll
        for (int u = 0; u < 2; u++) {
            const int e  = tid + 256 * u;
            const int r  = e >> 3;
            const int kw = (e & 7) * 2;
            float4 va = aR[u];
            float4 vg = gR[u];
            va.x *= vg.x; va.y *= vg.y; va.z *= vg.z; va.w *= vg.w;
            uint32_t h0, l0, h1, l1;
            bsplit2(va.x, va.y, h0, l0);
            bsplit2(va.z, va.w, h1, l1);
            *(uint2*)(ah_s + r * GST + kw) = make_uint2(h0, h1);
            *(uint2*)(al_s + r * GST + kw) = make_uint2(l0, l1);
        }
        if (ki + 1 < 8) {
            const int k0n = (ki + 1) * 32;
#pragma unroll
            for (int u = 0; u < 2; u++) {
                const int e  = tid + 256 * u;
                const int r  = e >> 3;
                const int kw = (e & 7) * 2;
                const size_t idx = (size_t)(m0 + r) * HC + k0n + kw * 2;
                aR[u] = *(const float4*)(g_o + idx);
                gR[u] = *(const float4*)(g_g + idx);
            }
            uint32_t* dh = bbh[(ki + 1) & 1];
            uint32_t* dl = bbl[(ki + 1) & 1];
            cp16(sptr(dh + bnl * GST + bkw4),
                 WPH + (size_t)(n0 + bnl) * 128 + (k0n >> 1) + bkw4);
            cp16(sptr(dl + bnl * GST + bkw4),
                 WPL + (size_t)(n0 + bnl) * 128 + (k0n >> 1) + bkw4);
            cp_commit();
            cp_wait1();
        } else {
            cp_wait0();
        }
        __syncthreads();

        const uint32_t* bh_s = bbh[ki & 1];
        const uint32_t* bl_s = bbl[ki & 1];

#pragma unroll
        for (int kc = 0; kc < 2; kc++) {
            uint32_t ah[2][4], al[2][4];
#pragma unroll
            for (int mt = 0; mt < 2; mt++) {
                const int rb = wm * 32 + mt * 16 + gid;
                ah[mt][0] = ah_s[(rb)     * GST + kc * 8 + m4];
                ah[mt][1] = ah_s[(rb + 8) * GST + kc * 8 + m4];
                ah[mt][2] = ah_s[(rb)     * GST + kc * 8 + m4 + 4];
                ah[mt][3] = ah_s[(rb + 8) * GST + kc * 8 + m4 + 4];
                al[mt][0] = al_s[(rb)     * GST + kc * 8 + m4];
                al[mt][1] = al_s[(rb + 8) * GST + kc * 8 + m4];
                al[mt][2] = al_s[(rb)     * GST + kc * 8 + m4 + 4];
                al[mt][3] = al_s[(rb + 8) * GST + kc * 8 + m4 + 4];
            }
#pragma unroll
            for (int nt = 0; nt < 2; nt++) {
                const int cb = wn * 16 + nt * 8 + gid;
                uint32_t bh0 = bh_s[cb * GST + kc * 8 + m4];
                uint32_t bh1 = bh_s[cb * GST + kc * 8 + m4 + 4];
                uint32_t bl0 = bl_s[cb * GST + kc * 8 + m4];
                uint32_t bl1 = bl_s[cb * GST + kc * 8 + m4 + 4];
#pragma unroll
                for (int mt = 0; mt < 2; mt++) {
                    mma_bf16(acc[mt][nt], ah[mt][0], ah[mt][1], ah[mt][2], ah[mt][3], bh0, bh1);
                    mma_bf16(acc[mt][nt], ah[mt][0], ah[mt][1], ah[mt][2], ah[mt][3], bl0, bl1);
                    mma_bf16(acc[mt][nt], al[mt][0], al[mt][1], al[mt][2], al[mt][3], bh0, bh1);
                }
            }
        }
    }

#pragma unroll
    for (int mt = 0; mt < 2; mt++) {
#pragma unroll
        for (int rr = 0; rr < 2; rr++) {
            const int row = m0 + wm * 32 + mt * 16 + gid + rr * 8;
#pragma unroll
            for (int nt = 0; nt < 2; nt++) {
                const int n = n0 + wn * 16 + nt * 8 + 2 * m4;
                float v0 = acc[mt][nt][rr * 2 + 0] + bo[n];
                float v1 = acc[mt][nt][rr * 2 + 1] + bo[n + 1];
                *(float2*)(out + (size_t)row * ND + n) = make_float2(v0, v1);
            }
        }
    }
}

// ---------------------------------------------------------------------------
// Launch
// ---------------------------------------------------------------------------
extern "C" void kernel_launch(void* const* d_in, const int* in_sizes, int n_in,
                              void* d_out, int out_size)
{
    const float* q_x       = (const float*)d_in[0];
    const float* kv_x      = (const float*)d_in[1];
    const float* bias_mask = (const float*)d_in[2];
    const float* bias_pair = (const float*)d_in[3];
    const float* wq        = (const float*)d_in[4];
    const float* wk        = (const float*)d_in[5];
    const float* wv        = (const float*)d_in[6];
    const float* wg        = (const float*)d_in[7];
    const float* bg        = (const float*)d_in[8];
    const float* wo        = (const float*)d_in[9];
    const float* bo        = (const float*)d_in[10];
    float* out             = (float*)d_out;

    const int smem_proj = (2 * 128 + 4 * 64) * GST * (int)sizeof(uint32_t);   // 40960
    const int smem_attn = (64 * K2ST + 32 * V2ST) * (int)sizeof(uint2)
                          + 64 * (int)sizeof(float)
                          + 2 * 128 * BST * (int)sizeof(float);                // 89600
    const int smem_out  = (2 * 64 + 4 * 64) * GST * (int)sizeof(uint32_t);    // 30720

    pack_w_kernel<<<dim3(128, 5), 256>>>(wq, wk, wv, wg, wo);

    {
        cudaFuncSetAttribute(proj_kernel, cudaFuncAttributeMaxDynamicSharedMemorySize, smem_proj);
        dim3 grid(HC / 64, NM / 128, 4);
        proj_kernel<<<grid, 256, smem_proj>>>(q_x, kv_x, bg);
    }
    {
        cudaFuncSetAttribute(attn_kernel, cudaFuncAttributeMaxDynamicSharedMemorySize, smem_attn);
        dim3 grid(NQ / 128, NB * NH);
        attn_kernel<<<grid, 256, smem_attn>>>(bias_mask, bias_pair);
    }
    {
        cudaFuncSetAttribute(out_kernel, cudaFuncAttributeMaxDynamicSharedMemorySize, smem_out);
        dim3 grid(ND / 64, NM / 64);
        out_kernel<<<grid, 256, smem_out>>>(bo, out);
    }
}